// round 7
// baseline (speedup 1.0000x reference)
#include <cuda_runtime.h>
#include <math.h>

#define DT 0.1f
#define EPS_STAT 0.01f

template <int BLOCK, int R>
__global__ void __launch_bounds__(BLOCK)
kalman_kernel(const float* __restrict__ in, float* __restrict__ out,
              const float* __restrict__ sa_p, const float* __restrict__ so_p,
              const float* __restrict__ si_p,
              int B, int n_est, int n_pred) {
    __shared__ float4 gt[16];                 // est: (K0, K1, s, 0)
    __shared__ float  st[64];                 // pred: s
    __shared__ float  buf[2][R * BLOCK * 5];  // double-buffered R-row staging

    const int tid = threadIdx.x;
    const int blockStart = blockIdx.x * BLOCK;
    const bool fullBlock = (blockStart + BLOCK <= B);
    const int b = min(blockStart + tid, B - 1);
    const int total = n_est + n_pred;

    // ---- thread 0: uniform covariance recursion -> tables ----
    if (tid == 0) {
        const float sa = *sa_p, so = *so_p, si = *si_p;
        const float g0  = DT * DT * 0.5f;
        const float q00 = sa * sa * (g0 * g0);
        const float q01 = sa * sa * (g0 * DT);
        const float q11 = sa * sa * (DT * DT);
        const float r   = so * so;
        const float eps2 = EPS_STAT * EPS_STAT;
        float P00 = si * si, P01 = 0.0f, P11 = si * si;
        for (int k = 0; k < n_est; k++) {
            float a = P00 + 2.0f * DT * P01 + DT * DT * P11 + q00;
            float c = P01 + DT * P11 + q01;
            float d = P11 + q11;
            P00 = a; P01 = c; P11 = d;
            float S = P00 + r, rs = 1.0f / S;
            float K0 = P00 * rs, K1 = P01 * rs;
            float omk = 1.0f - K0;
            float A00 = omk * P00;
            float A01 = omk * P01;
            float A10 = P01 - K1 * P00;
            float A11 = P11 - K1 * P01;
            P00 =  A00 * omk      + r * K0 * K0;
            P01 = -A00 * K1 + A01 + r * K0 * K1;
            P11 = -A10 * K1 + A11 + r * K1 * K1;
            gt[k] = make_float4(K0, K1, sqrtf(fmaxf(P00, eps2)), 0.0f);
        }
        for (int j = 0; j < n_pred; j++) {
            float a = P00 + 2.0f * DT * P01 + DT * DT * P11 + q00;
            float c = P01 + DT * P11 + q01;
            float d = P11 + q11;
            P00 = a; P01 = c; P11 = d;
            st[j] = sqrtf(fmaxf(P00, eps2));
        }
    }

    // ---- init state from rows 0,1 ----
    const float2* __restrict__ zin = reinterpret_cast<const float2*>(in);
    float2 z0 = zin[b];
    float2 z1 = zin[(size_t)B + b];
    float px = z0.x, py = z0.y;
    float vx = (z1.x - z0.x) * (1.0f / DT);
    float vy = (z1.y - z0.y) * (1.0f / DT);
    float2 z = z1;

    // constant zero slots, written once
    #pragma unroll
    for (int r = 0; r < R; r++) {
        buf[0][r * BLOCK * 5 + tid * 5 + 4] = 0.0f;
        buf[1][r * BLOCK * 5 + tid * 5 + 4] = 0.0f;
    }
    __syncthreads();  // tables + zeros visible

    // ---- copy-out indexing, hoisted (constant per thread) ----
    constexpr int ROWF4 = BLOCK * 5 / 4;                 // float4 per row (320)
    constexpr int FL = (R * ROWF4 + BLOCK - 1) / BLOCK;  // flush loads per thread (5)
    const long long rowF4o = (long long)B * 5 / 4;
    long long off[FL];
    #pragma unroll
    for (int u = 0; u < FL; u++) {
        int idx = tid + u * BLOCK;
        off[u] = (long long)(idx / ROWF4) * rowF4o + (idx % ROWF4);
    }
    float4* __restrict__ outB =
        reinterpret_cast<float4*>(out) + (long long)blockStart * 5 / 4;

    int t = 0, p = 0;
    while (t < total) {
        const int gcount = min(R, total - t);
        const int t0 = t;
        float* bp = buf[p];

        for (int r = 0; r < gcount; r++, t++) {
            px += DT * vx;
            py += DT * vy;
            float s;
            if (t < n_est) {
                float4 g = gt[t];
                float yx = z.x - px, yy = z.y - py;
                px += g.x * yx; vx += g.y * yx;
                py += g.x * yy; vy += g.y * yy;
                if (t + 1 < n_est) z = zin[(size_t)(t + 2) * B + b];
                s = g.z;
            } else {
                s = st[t - n_est];
            }
            if (fullBlock) {
                float* row = bp + r * BLOCK * 5 + tid * 5;
                row[0] = px; row[1] = py; row[2] = s; row[3] = s;
            } else if (blockStart + tid < B) {
                float* d = out + (long long)t * B * 5
                               + (long long)(blockStart + tid) * 5;
                d[0] = px; d[1] = py; d[2] = s; d[3] = s; d[4] = 0.0f;
            }
        }

        if (fullBlock) {
            __syncthreads();  // group fill done + prior-buffer copies done
            const float4* sb = reinterpret_cast<const float4*>(bp);
            float4* dst = outB + (long long)t0 * rowF4o;
            const int lim = gcount * ROWF4;
            #pragma unroll
            for (int u = 0; u < FL; u++) {
                int idx = tid + u * BLOCK;
                if (idx < lim) dst[off[u]] = sb[idx];
            }
        }
        p ^= 1;
    }
}

extern "C" void kernel_launch(void* const* d_in, const int* in_sizes, int n_in,
                              void* d_out, int out_size) {
    const float* inputs  = (const float*)d_in[0];
    const float* sigma_a = (const float*)d_in[1];
    const float* sigma_o = (const float*)d_in[2];
    const float* sigma_i = (const float*)d_in[3];

    const int T_OBS = 10;
    const int B = in_sizes[0] / (T_OBS * 2);
    const int n_est = T_OBS - 1;                // 9
    const int totalSteps = out_size / (B * 5);  // 39
    const int n_pred = totalSteps - n_est;      // 30

    constexpr int BLOCK = 256;
    constexpr int R = 4;
    const int grid = (B + BLOCK - 1) / BLOCK;
    kalman_kernel<BLOCK, R><<<grid, BLOCK>>>(inputs, (float*)d_out,
                                             sigma_a, sigma_o, sigma_i,
                                             B, n_est, n_pred);
}

// round 8
// speedup vs baseline: 1.0554x; 1.0554x over previous
#include <cuda_runtime.h>
#include <math.h>

#define DT 0.1f
#define EPS_STAT 0.01f

template <int BLOCK>
__global__ void __launch_bounds__(BLOCK)
kalman_kernel(const float* __restrict__ in, float* __restrict__ out,
              const float* __restrict__ sa_p, const float* __restrict__ so_p,
              const float* __restrict__ si_p,
              int B, int n_est, int n_pred) {
    __shared__ float4 gt[16];             // est: (K0, K1, s, 0)
    __shared__ float  st[64];             // pred: s
    __shared__ float  buf[2][BLOCK * 5];  // double-buffered rows, warp-partitioned

    const int tid  = threadIdx.x;
    const int lane = tid & 31;
    const int w    = tid >> 5;
    const int blockStart = blockIdx.x * BLOCK;
    const bool fullBlock = (blockStart + BLOCK <= B);
    const int b = min(blockStart + tid, B - 1);
    const int total = n_est + n_pred;

    // ---- thread 0: uniform covariance recursion -> tables ----
    if (tid == 0) {
        const float sa = *sa_p, so = *so_p, si = *si_p;
        const float g0  = DT * DT * 0.5f;
        const float q00 = sa * sa * (g0 * g0);
        const float q01 = sa * sa * (g0 * DT);
        const float q11 = sa * sa * (DT * DT);
        const float r   = so * so;
        const float eps2 = EPS_STAT * EPS_STAT;
        float P00 = si * si, P01 = 0.0f, P11 = si * si;
        for (int k = 0; k < n_est; k++) {
            float a = P00 + 2.0f * DT * P01 + DT * DT * P11 + q00;
            float c = P01 + DT * P11 + q01;
            float d = P11 + q11;
            P00 = a; P01 = c; P11 = d;
            float S = P00 + r, rs = 1.0f / S;
            float K0 = P00 * rs, K1 = P01 * rs;
            float omk = 1.0f - K0;
            float A00 = omk * P00;
            float A01 = omk * P01;
            float A10 = P01 - K1 * P00;
            float A11 = P11 - K1 * P01;
            P00 =  A00 * omk      + r * K0 * K0;
            P01 = -A00 * K1 + A01 + r * K0 * K1;
            P11 = -A10 * K1 + A11 + r * K1 * K1;
            gt[k] = make_float4(K0, K1, sqrtf(fmaxf(P00, eps2)), 0.0f);
        }
        for (int j = 0; j < n_pred; j++) {
            float a = P00 + 2.0f * DT * P01 + DT * DT * P11 + q00;
            float c = P01 + DT * P11 + q01;
            float d = P11 + q11;
            P00 = a; P01 = c; P11 = d;
            st[j] = sqrtf(fmaxf(P00, eps2));
        }
    }

    // constant zero slots (written once, never touched again)
    buf[0][tid * 5 + 4] = 0.0f;
    buf[1][tid * 5 + 4] = 0.0f;

    // ---- init state from rows 0,1 ----
    const float2* __restrict__ zin = reinterpret_cast<const float2*>(in);
    float2 z0 = zin[b];
    float2 z1 = zin[(size_t)B + b];
    float px = z0.x, py = z0.y;
    float vx = (z1.x - z0.x) * (1.0f / DT);
    float vy = (z1.y - z0.y) * (1.0f / DT);
    float2 z = z1;

    __syncthreads();  // tables + zero slots visible; ONLY block-wide sync

    // ---- warp-local staging regions & output pointers (hoisted) ----
    // warp w owns elements [32w, 32w+32) = 160 floats = 40 float4s per row
    float* const wbuf0 = &buf[0][w * 160];
    float* const wbuf1 = &buf[1][w * 160];
    const long long rowF4o = (long long)B * 5 / 4;
    float4* dst = reinterpret_cast<float4*>(out)
                + (long long)blockStart * 5 / 4 + w * 40 + lane;
    const bool extra = (lane < 8);

    for (int t = 0; t < total; t++) {
        // mean predict
        px += DT * vx;
        py += DT * vy;
        float s;
        if (t < n_est) {
            float4 g = gt[t];                 // broadcast LDS.128
            float yx = z.x - px, yy = z.y - py;
            px += g.x * yx; vx += g.y * yx;
            py += g.x * yy; vy += g.y * yy;
            if (t + 1 < n_est) z = zin[(size_t)(t + 2) * B + b];
            s = g.z;
        } else {
            s = st[t - n_est];
        }

        if (fullBlock) {
            float* wb = (t & 1) ? wbuf1 : wbuf0;
            float* row = wb + lane * 5;
            row[0] = px; row[1] = py; row[2] = s; row[3] = s;
            __syncwarp();  // intra-warp exchange only — no block-wide wait
            const float4* sb = reinterpret_cast<const float4*>(wb);
            float4 v0 = sb[lane];
            dst[0] = v0;
            if (extra) {
                float4 v1 = sb[lane + 32];
                dst[32] = v1;
            }
        } else if (blockStart + tid < B) {
            float* d = out + (long long)t * B * 5
                           + (long long)(blockStart + tid) * 5;
            d[0] = px; d[1] = py; d[2] = s; d[3] = s; d[4] = 0.0f;
        }
        dst += rowF4o;
        // next iteration writes the other warp-local buffer; two syncwarps
        // separate any reuse of this buffer -> no read/write hazard.
    }
}

extern "C" void kernel_launch(void* const* d_in, const int* in_sizes, int n_in,
                              void* d_out, int out_size) {
    const float* inputs  = (const float*)d_in[0];
    const float* sigma_a = (const float*)d_in[1];
    const float* sigma_o = (const float*)d_in[2];
    const float* sigma_i = (const float*)d_in[3];

    const int T_OBS = 10;
    const int B = in_sizes[0] / (T_OBS * 2);
    const int n_est = T_OBS - 1;                // 9
    const int totalSteps = out_size / (B * 5);  // 39
    const int n_pred = totalSteps - n_est;      // 30

    constexpr int BLOCK = 256;
    const int grid = (B + BLOCK - 1) / BLOCK;
    kalman_kernel<BLOCK><<<grid, BLOCK>>>(inputs, (float*)d_out,
                                          sigma_a, sigma_o, sigma_i,
                                          B, n_est, n_pred);
}

// round 10
// speedup vs baseline: 1.1315x; 1.0721x over previous
#include <cuda_runtime.h>
#include <math.h>

#define DT 0.1f
#define EPS_STAT 0.01f

template <int BLOCK>
__global__ void __launch_bounds__(BLOCK)
kalman_kernel(const float* __restrict__ in, float* __restrict__ out,
              const float* __restrict__ sa_p, const float* __restrict__ so_p,
              const float* __restrict__ si_p,
              int B, int n_est, int n_pred) {
    __shared__ float4 gt[16];                  // est: (K0, K1, s, 0)
    __shared__ float  st[64];                  // pred: s
    __shared__ float  ring[5][BLOCK * 5];      // 5-deep warp-partitioned staging

    const int tid  = threadIdx.x;
    const int lane = tid & 31;
    const int w    = tid >> 5;
    const int blockStart = blockIdx.x * BLOCK;
    const bool fullBlock = (blockStart + BLOCK <= B);
    const int b = min(blockStart + tid, B - 1);
    const int total = n_est + n_pred;

    // ---- thread 0: uniform covariance recursion -> tables ----
    if (tid == 0) {
        const float sa = *sa_p, so = *so_p, si = *si_p;
        const float g0  = DT * DT * 0.5f;
        const float q00 = sa * sa * (g0 * g0);
        const float q01 = sa * sa * (g0 * DT);
        const float q11 = sa * sa * (DT * DT);
        const float r   = so * so;
        const float eps2 = EPS_STAT * EPS_STAT;
        float P00 = si * si, P01 = 0.0f, P11 = si * si;
        for (int k = 0; k < n_est; k++) {
            float a = P00 + 2.0f * DT * P01 + DT * DT * P11 + q00;
            float c = P01 + DT * P11 + q01;
            float d = P11 + q11;
            P00 = a; P01 = c; P11 = d;
            float S = P00 + r, rs = 1.0f / S;
            float K0 = P00 * rs, K1 = P01 * rs;
            float omk = 1.0f - K0;
            float A00 = omk * P00;
            float A01 = omk * P01;
            float A10 = P01 - K1 * P00;
            float A11 = P11 - K1 * P01;
            P00 =  A00 * omk      + r * K0 * K0;
            P01 = -A00 * K1 + A01 + r * K0 * K1;
            P11 = -A10 * K1 + A11 + r * K1 * K1;
            gt[k] = make_float4(K0, K1, sqrtf(fmaxf(P00, eps2)), 0.0f);
        }
        for (int j = 0; j < n_pred; j++) {
            float a = P00 + 2.0f * DT * P01 + DT * DT * P11 + q00;
            float c = P01 + DT * P11 + q01;
            float d = P11 + q11;
            P00 = a; P01 = c; P11 = d;
            st[j] = sqrtf(fmaxf(P00, eps2));
        }
    }

    // constant zero slots in all ring buffers (written once)
    #pragma unroll
    for (int r = 0; r < 5; r++) ring[r][tid * 5 + 4] = 0.0f;

    // ---- init state from rows 0,1 ----
    const float2* __restrict__ zin = reinterpret_cast<const float2*>(in);
    float2 z0 = zin[b];
    float2 z1 = zin[(size_t)B + b];
    float px = z0.x, py = z0.y;
    float vx = (z1.x - z0.x) * (1.0f / DT);
    float vy = (z1.y - z0.y) * (1.0f / DT);
    float2 z = z1;

    __syncthreads();  // tables + zero slots visible (only block-wide sync)

    // ---- warp-local staging + hoisted output pointers ----
    float* const wbase = &ring[0][w * 160];          // warp region in ring[0]
    constexpr int RSTRIDE = BLOCK * 5;               // floats between ring bufs
    const int rowF4o = B * 5 / 4;                    // float4s per output row
    float4* dst = reinterpret_cast<float4*>(out)
                + (long long)blockStart * 5 / 4 + w * 40 + lane;
    const bool extra = (lane < 8);

    // ================= estimation phase =================
    for (int t = 0; t < n_est; t++) {
        px += DT * vx;
        py += DT * vy;
        float4 g = gt[t];
        float yx = z.x - px, yy = z.y - py;
        px += g.x * yx; vx += g.y * yx;
        py += g.x * yy; vy += g.y * yy;
        if (t + 1 < n_est) z = zin[(size_t)(t + 2) * B + b];
        float s = g.z;

        if (fullBlock) {
            float* row = wbase + (t & 1) * RSTRIDE + lane * 5;
            row[0] = px; row[1] = py; row[2] = s; row[3] = s;
            __syncwarp();
            const float4* sb = reinterpret_cast<const float4*>(
                wbase + (t & 1) * RSTRIDE);
            dst[0] = sb[lane];
            if (extra) dst[32] = sb[lane + 32];
        } else if (blockStart + tid < B) {
            float* d = out + (long long)t * B * 5
                           + (long long)(blockStart + tid) * 5;
            d[0] = px; d[1] = py; d[2] = s; d[3] = s; d[4] = 0.0f;
        }
        dst += rowF4o;
    }

    // ================= prediction phase (closed-form, 5-row groups) =================
    int t = n_est;
    if (fullBlock) {
        __syncwarp();  // est-phase reads of ring[0], ring[1] complete
        for (; t + 5 <= total; t += 5) {
            #pragma unroll
            for (int r = 0; r < 5; r++) {
                const int jp = t + r - n_est;
                const float tt = (float)(jp + 1) * DT;
                const float qx = fmaf(tt, vx, px);
                const float qy = fmaf(tt, vy, py);
                const float s  = st[jp];
                float* row = wbase + r * RSTRIDE + lane * 5;
                row[0] = qx; row[1] = qy; row[2] = s; row[3] = s;
            }
            __syncwarp();
            #pragma unroll
            for (int r = 0; r < 5; r++) {
                const float4* sb = reinterpret_cast<const float4*>(
                    wbase + r * RSTRIDE);
                float4* d = dst + r * rowF4o;
                d[0] = sb[lane];
                if (extra) d[32] = sb[lane + 32];
            }
            __syncwarp();
            dst += 5 * rowF4o;
        }
        // remainder rows
        for (; t < total; t++) {
            const int jp = t - n_est;
            const float tt = (float)(jp + 1) * DT;
            const float qx = fmaf(tt, vx, px);
            const float qy = fmaf(tt, vy, py);
            const float s  = st[jp];
            float* row = wbase + lane * 5;
            row[0] = qx; row[1] = qy; row[2] = s; row[3] = s;
            __syncwarp();
            const float4* sb = reinterpret_cast<const float4*>(wbase);
            dst[0] = sb[lane];
            if (extra) dst[32] = sb[lane + 32];
            __syncwarp();
            dst += rowF4o;
        }
    } else if (blockStart + tid < B) {
        for (; t < total; t++) {
            const int jp = t - n_est;
            const float tt = (float)(jp + 1) * DT;
            const float qx = fmaf(tt, vx, px);
            const float qy = fmaf(tt, vy, py);
            const float s  = st[jp];
            float* d = out + (long long)t * B * 5
                           + (long long)(blockStart + tid) * 5;
            d[0] = qx; d[1] = qy; d[2] = s; d[3] = s; d[4] = 0.0f;
        }
    }
}

extern "C" void kernel_launch(void* const* d_in, const int* in_sizes, int n_in,
                              void* d_out, int out_size) {
    const float* inputs  = (const float*)d_in[0];
    const float* sigma_a = (const float*)d_in[1];
    const float* sigma_o = (const float*)d_in[2];
    const float* sigma_i = (const float*)d_in[3];

    const int T_OBS = 10;
    const int B = in_sizes[0] / (T_OBS * 2);
    const int n_est = T_OBS - 1;                // 9
    const int totalSteps = out_size / (B * 5);  // 39
    const int n_pred = totalSteps - n_est;      // 30

    constexpr int BLOCK = 256;
    const int grid = (B + BLOCK - 1) / BLOCK;
    kalman_kernel<BLOCK><<<grid, BLOCK>>>(inputs, (float*)d_out,
                                          sigma_a, sigma_o, sigma_i,
                                          B, n_est, n_pred);
}